// round 4
// baseline (speedup 1.0000x reference)
#include <cuda_runtime.h>
#include <cuda_bf16.h>
#include <cstdint>

// ---------------- problem constants ----------------
#define Bv    8
#define P0v   20000
#define P1v   5000
#define P2v   1250
#define Mv    10
#define Wv    9
#define C0v   3
#define C1v   64
#define C2v   128
#define K2v   576            // W*C1
#define NROW  (Bv*P1v)       // 40000 GEMM rows
#define KDv   (P2v*C2v)      // 160000
#define LOUT  512            // 2*LATENT
#define KSPLIT 25
#define KCHUNK (KDv/KSPLIT)  // 6400

// ---------------- device scratch (allocation-free rule: __device__ globals) ----
__device__ float g_h0[Bv*(size_t)P0v*C1v];    // 40.96 MB
__device__ float g_h1[Bv*(size_t)P1v*C1v];    // 10.24 MB
__device__ float g_S [Bv*(size_t)P1v*K2v];    // 92.16 MB
__device__ float g_h2[Bv*(size_t)P1v*C2v];    // 20.48 MB
__device__ float g_h3[Bv*(size_t)P2v*C2v];    //  5.12 MB  (= f)
__device__ float g_Wmat[K2v*C2v];             // 576x128
__device__ float g_part[KSPLIT*Bv*LOUT];

// ---------------- f32x2 packed-FMA helpers (sm_103a) ----------------
__device__ __forceinline__ unsigned long long pack2(float a, float b) {
    unsigned long long r;
    asm("mov.b64 %0, {%1, %2};" : "=l"(r) : "f"(a), "f"(b));
    return r;
}
__device__ __forceinline__ void fma2(unsigned long long& d,
                                     unsigned long long a, unsigned long long b) {
    asm("fma.rn.f32x2 %0, %1, %2, %0;" : "+l"(d) : "l"(a), "l"(b));
}
__device__ __forceinline__ float2 unpack2(unsigned long long v) {
    float2 r;
    asm("mov.b64 {%0, %1}, %2;" : "=f"(r.x), "=f"(r.y) : "l"(v));
    return r;
}
__device__ __forceinline__ float elu(float x) {
    return x > 0.f ? x : expm1f(x);
}

// ================= kernel 1: conv0 + ELU  ==========================
// block per point p (P0 blocks), 512 threads: tx = out-channel (64), ty = b (8)
__global__ void __launch_bounds__(512) conv0_kernel(
    const float* __restrict__ x, const int* __restrict__ nb0,
    const float* __restrict__ w0, const float* __restrict__ bias0,
    const float* __restrict__ ww0)
{
    __shared__ float Wt[27][C1v];      // Wt[k][o] = w0[w*192 + o*3 + i], k=w*3+i
    __shared__ float wws[Mv*Wv];       // 90
    __shared__ int   nbs[Mv];
    __shared__ float xg[Bv][Mv*C0v];   // gathered x (0 if masked)
    __shared__ float s[Bv][28];        // s[b][w*3+i], padded

    const int p = blockIdx.x;
    const int t = threadIdx.x;

    for (int e = t; e < 27*C1v; e += 512) {
        int k = e / C1v, o = e % C1v;
        Wt[k][o] = w0[(k/3)*192 + o*3 + (k%3)];
    }
    if (t < Mv)    nbs[t] = nb0[p*Mv + t];
    if (t < Mv*Wv) wws[t] = ww0[p*Mv*Wv + t];
    __syncthreads();

    if (t < Bv*Mv*C0v) {               // 240 threads gather x
        int b = t / (Mv*C0v), r = t % (Mv*C0v);
        int m = r / C0v, i = r % C0v;
        int idx = nbs[m];
        xg[b][r] = (idx < P0v) ? x[((size_t)b*P0v + idx)*C0v + i] : 0.f;
    }
    __syncthreads();

    if (t < Bv*27) {                   // 216 threads compute s
        int b = t / 27, k = t % 27;
        int w = k / 3, i = k % 3;
        float acc = 0.f;
        #pragma unroll
        for (int m = 0; m < Mv; m++) acc += wws[m*Wv + w] * xg[b][m*3 + i];
        s[b][k] = acc;
    }
    __syncthreads();

    const int tx = t & 63, ty = t >> 6;
    float acc = bias0[tx];
    #pragma unroll
    for (int k = 0; k < 27; k++) acc += s[ty][k] * Wt[k][tx];
    g_h0[((size_t)ty*P0v + p)*C1v + tx] = elu(acc);
}

// ================= pooling (pool1 / pool3) + ELU ===================
// STAGE 0: g_h0 (P0, C1) -> g_h1 (P1);  STAGE 1: g_h2 (P1, C2) -> g_h3 (P2)
// NOTE: buffers resolved in DEVICE code — never pass __device__ symbols from host.
template<int C, int Pin, int Pout, int STAGE>
__global__ void pool_kernel(const int* __restrict__ nb,
                            const float* __restrict__ pnb)
{
    const float* __restrict__ hin  = (STAGE == 0) ? g_h0 : g_h2;
    float*       __restrict__ hout = (STAGE == 0) ? g_h1 : g_h3;

    __shared__ int   nbs[Mv];
    __shared__ float wt[Mv];
    const int p = blockIdx.x;
    const int t = threadIdx.x;          // C * 8 threads
    if (t < Mv) {
        int idx = nb[p*Mv + t];
        nbs[t] = idx;
        wt[t]  = (idx < Pin) ? fabsf(pnb[p*Mv + t]) : 0.f;
    }
    __syncthreads();
    float denom = 1e-8f;
    #pragma unroll
    for (int m = 0; m < Mv; m++) denom += wt[m];

    const int c = t % C, b = t / C;
    float acc = 0.f;
    #pragma unroll
    for (int m = 0; m < Mv; m++) {
        int idx = nbs[m];
        if (idx < Pin) acc += wt[m] * hin[((size_t)b*Pin + idx)*C + c];
    }
    acc /= denom;
    hout[((size_t)b*Pout + p)*C + c] = elu(acc);
}

// ================= kernel 3a: S[b,p,w,i] = sum_m ww2[p,m,w]*h1[b,nb,i] ====
__global__ void __launch_bounds__(512) conv2s_kernel(
    const int* __restrict__ nb2, const float* __restrict__ ww2)
{
    __shared__ int   nbs[Mv];
    __shared__ float wws[Mv*Wv];
    const int p = blockIdx.x;
    const int t = threadIdx.x;           // 512: i = t%64, b = t/64
    if (t < Mv)    nbs[t] = nb2[p*Mv + t];
    if (t < Mv*Wv) wws[t] = ww2[p*Mv*Wv + t];
    __syncthreads();

    const int i = t & 63, b = t >> 6;
    float acc[Wv];
    #pragma unroll
    for (int w = 0; w < Wv; w++) acc[w] = 0.f;
    #pragma unroll
    for (int m = 0; m < Mv; m++) {
        int idx = nbs[m];
        if (idx < P1v) {
            float v = g_h1[((size_t)b*P1v + idx)*C1v + i];
            #pragma unroll
            for (int w = 0; w < Wv; w++) acc[w] += wws[m*Wv + w] * v;
        }
    }
    const size_t r = (size_t)b*P1v + p;
    #pragma unroll
    for (int w = 0; w < Wv; w++) g_S[(r*Wv + w)*C1v + i] = acc[w];
}

// ================= kernel: transpose weights2 -> Wmat[k][o] ========
__global__ void wmat_kernel(const float* __restrict__ w2)
{
    int e = blockIdx.x * 256 + threadIdx.x;
    if (e < K2v*C2v) {
        int k = e / C2v, o = e % C2v;
        g_Wmat[e] = w2[(k >> 6)*(C2v*C1v) + o*C1v + (k & 63)];
    }
}

// ================= kernel 3b: SGEMM h2 = ELU(S @ Wmat + bias2) =====
// 128x128 tile, 256 threads, 8x8 per thread, fp32x2 packed FMA
__global__ void __launch_bounds__(256) gemm_kernel(const float* __restrict__ bias2)
{
    __shared__ float As[8][128];   // As[kk][m] (transposed)
    __shared__ float Bs[8][128];   // Bs[kk][o]

    const int m0 = blockIdx.x * 128;
    const int t  = threadIdx.x;
    const int tx = t & 15, ty = t >> 4;      // 16x16 threads

    unsigned long long acc[8][4];
    #pragma unroll
    for (int i = 0; i < 8; i++)
        #pragma unroll
        for (int j = 0; j < 4; j++) acc[i][j] = 0ull;

    const int a_lm   = t >> 1;        // 0..127
    const int a_kseg = (t & 1) * 4;   // 0 or 4
    const int b_kk   = t >> 5;        // 0..7
    const int b_oseg = (t & 31) * 4;  // 0..124
    const int a_row  = m0 + a_lm;
    const bool a_ok  = (a_row < NROW);
    const float* Ap  = g_S + (size_t)a_row * K2v + a_kseg;

    for (int k0 = 0; k0 < K2v; k0 += 8) {
        float4 av = make_float4(0.f,0.f,0.f,0.f);
        if (a_ok) av = *(const float4*)(Ap + k0);
        float4 bv = *(const float4*)(g_Wmat + (k0 + b_kk)*C2v + b_oseg);
        __syncthreads();
        As[a_kseg+0][a_lm] = av.x;
        As[a_kseg+1][a_lm] = av.y;
        As[a_kseg+2][a_lm] = av.z;
        As[a_kseg+3][a_lm] = av.w;
        *(float4*)&Bs[b_kk][b_oseg] = bv;
        __syncthreads();

        #pragma unroll
        for (int kk = 0; kk < 8; kk++) {
            float a[8];
            *(float4*)&a[0] = *(const float4*)&As[kk][ty*8];
            *(float4*)&a[4] = *(const float4*)&As[kk][ty*8 + 4];
            unsigned long long b2[4];
            const unsigned long long* bp = (const unsigned long long*)&Bs[kk][tx*8];
            b2[0] = bp[0]; b2[1] = bp[1]; b2[2] = bp[2]; b2[3] = bp[3];
            #pragma unroll
            for (int i = 0; i < 8; i++) {
                unsigned long long a2 = pack2(a[i], a[i]);
                #pragma unroll
                for (int j = 0; j < 4; j++) fma2(acc[i][j], a2, b2[j]);
            }
        }
    }

    float bia[8];
    #pragma unroll
    for (int j = 0; j < 8; j++) bia[j] = bias2[tx*8 + j];

    #pragma unroll
    for (int i = 0; i < 8; i++) {
        int row = m0 + ty*8 + i;
        if (row < NROW) {
            #pragma unroll
            for (int j = 0; j < 4; j++) {
                float2 v = unpack2(acc[i][j]);
                float2 o;
                o.x = elu(v.x + bia[2*j+0]);
                o.y = elu(v.y + bia[2*j+1]);
                *(float2*)&g_h2[(size_t)row*C2v + tx*8 + 2*j] = o;
            }
        }
    }
}

// ================= kernel 5: final dense (HBM streaming) ===========
// grid (16, KSPLIT), 256 threads = 8 warps; warp owns 4 output rows (l),
// lanes split K; accumulators in registers, warp-shfl reduce, partials out.
__global__ void __launch_bounds__(256) dense_kernel(
    const float* __restrict__ Wm, const float* __restrict__ Ws)
{
    const int warp = threadIdx.x >> 5, lane = threadIdx.x & 31;
    const int l0 = blockIdx.x * 32 + warp * 4;
    const int ks = blockIdx.y;
    const int k0 = ks * KCHUNK;

    const float* Wp = (l0 < 256) ? (Wm + (size_t)l0 * KDv)
                                 : (Ws + (size_t)(l0 - 256) * KDv);
    const float* f = g_h3;

    float acc[4][8];
    #pragma unroll
    for (int j = 0; j < 4; j++)
        #pragma unroll
        for (int b = 0; b < 8; b++) acc[j][b] = 0.f;

    for (int k = k0 + lane; k < k0 + KCHUNK; k += 32) {
        float fv[8];
        #pragma unroll
        for (int b = 0; b < 8; b++) fv[b] = f[(size_t)b*KDv + k];
        #pragma unroll
        for (int j = 0; j < 4; j++) {
            float wv = Wp[(size_t)j*KDv + k];
            #pragma unroll
            for (int b = 0; b < 8; b++) acc[j][b] += wv * fv[b];
        }
    }

    #pragma unroll
    for (int j = 0; j < 4; j++)
        #pragma unroll
        for (int b = 0; b < 8; b++) {
            float v = acc[j][b];
            #pragma unroll
            for (int off = 16; off > 0; off >>= 1)
                v += __shfl_xor_sync(0xffffffffu, v, off);
            acc[j][b] = v;
        }

    if (lane == 0) {
        #pragma unroll
        for (int j = 0; j < 4; j++)
            #pragma unroll
            for (int b = 0; b < 8; b++)
                g_part[((size_t)ks*Bv + b)*LOUT + l0 + j] = acc[j][b];
    }
}

__global__ void reduce_kernel(const float* __restrict__ bm,
                              const float* __restrict__ bs,
                              float* __restrict__ out)
{
    int e = blockIdx.x * 256 + threadIdx.x;   // 4096
    if (e >= Bv*LOUT) return;
    int b = e >> 9, l = e & 511;
    float acc = (l < 256) ? bm[l] : bs[l - 256];
    #pragma unroll 5
    for (int ks = 0; ks < KSPLIT; ks++)
        acc += g_part[((size_t)ks*Bv + b)*LOUT + l];
    out[e] = acc;
}

// ================= launch =========================================
extern "C" void kernel_launch(void* const* d_in, const int* in_sizes, int n_in,
                              void* d_out, int out_size)
{
    const float* x    = (const float*)d_in[0];
    const int*   nb0  = (const int*)  d_in[1];
    const int*   nb1  = (const int*)  d_in[2];
    const int*   nb2  = (const int*)  d_in[3];
    const int*   nb3  = (const int*)  d_in[4];
    const float* w0   = (const float*)d_in[5];
    const float* bia0 = (const float*)d_in[6];
    const float* ww0  = (const float*)d_in[7];
    const float* pn1  = (const float*)d_in[8];
    const float* w2   = (const float*)d_in[9];
    const float* bia2 = (const float*)d_in[10];
    const float* ww2  = (const float*)d_in[11];
    const float* pn3  = (const float*)d_in[12];
    const float* Wm   = (const float*)d_in[13];
    const float* bm   = (const float*)d_in[14];
    const float* Ws   = (const float*)d_in[15];
    const float* bs   = (const float*)d_in[16];
    float* out = (float*)d_out;

    conv0_kernel<<<P0v, 512>>>(x, nb0, w0, bia0, ww0);
    pool_kernel<C1v, P0v, P1v, 0><<<P1v, C1v*Bv>>>(nb1, pn1);
    conv2s_kernel<<<P1v, 512>>>(nb2, ww2);
    wmat_kernel<<<(K2v*C2v + 255)/256, 256>>>(w2);
    gemm_kernel<<<(NROW + 127)/128, 256>>>(bia2);
    pool_kernel<C2v, P1v, P2v, 1><<<P2v, C2v*Bv>>>(nb3, pn3);
    dense_kernel<<<dim3(16, KSPLIT), 256>>>(Wm, Ws);
    reduce_kernel<<<(Bv*LOUT + 255)/256, 256>>>(bm, bs, out);
}

// round 7
// speedup vs baseline: 1.3337x; 1.3337x over previous
#include <cuda_runtime.h>
#include <cuda_bf16.h>
#include <mma.h>
#include <cstdint>

using namespace nvcuda;

// ---------------- problem constants ----------------
#define Bv    8
#define P0v   20000
#define P1v   5000
#define P2v   1250
#define Mv    10
#define Wv    9
#define C0v   3
#define C1v   64
#define C2v   128
#define K2v   576            // W*C1
#define NROW  (Bv*P1v)       // 40000 GEMM rows
#define KDv   (P2v*C2v)      // 160000
#define LOUT  512            // 2*LATENT
#define KSPLIT 25
#define KCHUNK (KDv/KSPLIT)  // 6400

// ---------------- device scratch ----------------
__device__ __align__(128) float g_h0[Bv*(size_t)P0v*C1v];    // 40.96 MB
__device__ __align__(128) float g_h1[Bv*(size_t)P1v*C1v];    // 10.24 MB
__device__ __align__(128) float g_h2[Bv*(size_t)P1v*C2v];    // 20.48 MB
__device__ __align__(128) float g_h3[Bv*(size_t)P2v*C2v];    //  5.12 MB
__device__ __align__(128) __nv_bfloat16 g_Shi[(size_t)NROW*K2v];  // 46.08 MB
__device__ __align__(128) __nv_bfloat16 g_Slo[(size_t)NROW*K2v];  // 46.08 MB
__device__ __align__(128) __nv_bfloat16 g_Whi[K2v*C2v];
__device__ __align__(128) __nv_bfloat16 g_Wlo[K2v*C2v];
__device__ __align__(128) float g_part[KSPLIT*Bv*LOUT];

__device__ __forceinline__ float elu(float x) {
    return x > 0.f ? x : expm1f(x);
}
__device__ __forceinline__ uint32_t smem_to_u32(const void* p) {
    uint32_t a;
    asm("{ .reg .u64 tmp; cvta.to.shared.u64 tmp, %1; cvt.u32.u64 %0, tmp; }"
        : "=r"(a) : "l"(p));
    return a;
}
__device__ __forceinline__ void cp_async16(uint32_t d, const void* s, int srcsize) {
    asm volatile("cp.async.ca.shared.global [%0], [%1], 16, %2;"
                 :: "r"(d), "l"(s), "r"(srcsize) : "memory");
}

// ================= kernel 1: conv0 + ELU (8 points per block) ======
#define CPTS 8
__global__ void __launch_bounds__(512) conv0_kernel(
    const float* __restrict__ x, const int* __restrict__ nb0,
    const float* __restrict__ w0, const float* __restrict__ bias0,
    const float* __restrict__ ww0)
{
    __shared__ float Wt[27][C1v];
    __shared__ float wws[CPTS][Mv*Wv];
    __shared__ int   nbs[CPTS][Mv];
    __shared__ float xg[CPTS][Bv][32];
    __shared__ float s[CPTS][Bv][28];

    const int p0 = blockIdx.x * CPTS;
    const int t  = threadIdx.x;

    for (int e = t; e < 27*C1v; e += 512) {
        int k = e >> 6, o = e & 63;
        Wt[k][o] = w0[(k/3)*192 + o*3 + (k%3)];
    }
    if (t < CPTS*Mv) nbs[t/Mv][t%Mv] = nb0[p0*Mv + t];
    for (int e = t; e < CPTS*Mv*Wv; e += 512)
        wws[e/(Mv*Wv)][e%(Mv*Wv)] = ww0[p0*Mv*Wv + e];
    __syncthreads();

    for (int e = t; e < CPTS*Bv*Mv*C0v; e += 512) {   // 1920
        int j = e / 240, r = e % 240;
        int b = r / 30, q = r % 30;
        int m = q / 3, i = q % 3;
        int idx = nbs[j][m];
        xg[j][b][q] = (idx < P0v) ? x[((size_t)b*P0v + idx)*C0v + i] : 0.f;
    }
    __syncthreads();

    for (int e = t; e < CPTS*Bv*27; e += 512) {       // 1728
        int j = e / 216, r = e % 216;
        int b = r / 27, k = r % 27;
        int w = k / 3, i = k % 3;
        float acc = 0.f;
        #pragma unroll
        for (int m = 0; m < Mv; m++) acc += wws[j][m*Wv + w] * xg[j][b][m*3 + i];
        s[j][b][k] = acc;
    }
    __syncthreads();

    const int tx = t & 63, ty = t >> 6;
    const float bia = bias0[tx];
    #pragma unroll
    for (int j = 0; j < CPTS; j++) {
        float acc = bia;
        #pragma unroll
        for (int k = 0; k < 27; k++) acc += s[j][ty][k] * Wt[k][tx];
        g_h0[((size_t)ty*P0v + p0 + j)*C1v + tx] = elu(acc);
    }
}

// ================= pooling (pool1 / pool3) + ELU ===================
template<int C, int Pin, int Pout, int STAGE>
__global__ void pool_kernel(const int* __restrict__ nb,
                            const float* __restrict__ pnb)
{
    const float* __restrict__ hin  = (STAGE == 0) ? g_h0 : g_h2;
    float*       __restrict__ hout = (STAGE == 0) ? g_h1 : g_h3;

    __shared__ int   nbs[Mv];
    __shared__ float wt[Mv];
    const int p = blockIdx.x;
    const int t = threadIdx.x;
    if (t < Mv) {
        int idx = nb[p*Mv + t];
        nbs[t] = idx;
        wt[t]  = (idx < Pin) ? fabsf(pnb[p*Mv + t]) : 0.f;
    }
    __syncthreads();
    float denom = 1e-8f;
    #pragma unroll
    for (int m = 0; m < Mv; m++) denom += wt[m];

    const int c = t % C, b = t / C;
    float acc = 0.f;
    #pragma unroll
    for (int m = 0; m < Mv; m++) {
        int idx = nbs[m];
        if (idx < Pin) acc += wt[m] * hin[((size_t)b*Pin + idx)*C + c];
    }
    acc /= denom;
    hout[((size_t)b*Pout + p)*C + c] = elu(acc);
}

// ====== conv2 stage A: S[b,p,w,i] -> bf16 hi/lo split planes =======
__global__ void __launch_bounds__(512) conv2s_kernel(
    const int* __restrict__ nb2, const float* __restrict__ ww2)
{
    __shared__ int   nbs[Mv];
    __shared__ float wws[Mv*Wv];
    const int p = blockIdx.x;
    const int t = threadIdx.x;
    if (t < Mv)    nbs[t] = nb2[p*Mv + t];
    if (t < Mv*Wv) wws[t] = ww2[p*Mv*Wv + t];
    __syncthreads();

    const int i = t & 63, b = t >> 6;
    float acc[Wv];
    #pragma unroll
    for (int w = 0; w < Wv; w++) acc[w] = 0.f;
    #pragma unroll
    for (int m = 0; m < Mv; m++) {
        int idx = nbs[m];
        if (idx < P1v) {
            float v = g_h1[((size_t)b*P1v + idx)*C1v + i];
            #pragma unroll
            for (int w = 0; w < Wv; w++) acc[w] += wws[m*Wv + w] * v;
        }
    }
    const size_t r = (size_t)b*P1v + p;
    #pragma unroll
    for (int w = 0; w < Wv; w++) {
        size_t idx = (r*Wv + w)*C1v + i;        // = r*576 + w*64 + i
        __nv_bfloat16 hi = __float2bfloat16(acc[w]);
        g_Shi[idx] = hi;
        g_Slo[idx] = __float2bfloat16(acc[w] - __bfloat162float(hi));
    }
}

// ====== weights2 -> Wmat[k][n], split bf16 hi/lo ==================
__global__ void wmat_split_kernel(const float* __restrict__ w2)
{
    int e = blockIdx.x * 256 + threadIdx.x;
    if (e < K2v*C2v) {
        int k = e >> 7, n = e & 127;
        float v = w2[(k >> 6)*(C2v*C1v) + n*C1v + (k & 63)];
        __nv_bfloat16 hi = __float2bfloat16(v);
        g_Whi[e] = hi;
        g_Wlo[e] = __float2bfloat16(v - __bfloat162float(hi));
    }
}

// ================= wmma bf16x3 GEMM: h2 = ELU(S @ W + bias2) =======
// CTA 128x128, 256 thr (warps 4x2 -> warp tile 32x64), k-step 16,
// cp.async double-buffered smem; A ldm=24, B ldm=136 (conflict-free LDSM).
#define GKS    16
#define GNST   (K2v/GKS)        // 36
#define A_PLe  3072             // 128*24 elems
#define B_PLe  2176             // 16*136 elems
#define STGe   (2*A_PLe + 2*B_PLe)   // 10496 elems = 20992 B
#define STGb   (2*STGe)              // bytes per stage
#define EPI_LD 132
#define GEMM_SMEM (128*EPI_LD*4)     // 67584 B (>= 2*STGb = 41984)

__global__ void __launch_bounds__(256) gemm_wmma_kernel(const float* __restrict__ bias2)
{
    extern __shared__ char sm[];
    __nv_bfloat16* smb = (__nv_bfloat16*)sm;
    const uint32_t sb = smem_to_u32(sm);
    const int t = threadIdx.x;
    const int warp = t >> 5;
    const int wm = warp & 3, wn = warp >> 2;    // 4 x 2
    const int m0 = blockIdx.x * 128;

    // loader thread mapping
    const int a_row = t >> 1, a_ks = (t & 1) * 8;
    const int b_kr  = t >> 4, b_ns = (t & 15) * 8;
    const int g_arow = m0 + a_row;
    const int a_sz  = (g_arow < NROW) ? 16 : 0;
    const int a_cl  = (g_arow < NROW) ? g_arow : 0;

    wmma::fragment<wmma::accumulator, 16, 16, 16, float> acc[2][4];
    #pragma unroll
    for (int i = 0; i < 2; i++)
        #pragma unroll
        for (int j = 0; j < 4; j++) wmma::fill_fragment(acc[i][j], 0.f);

    auto stage_load = [&](int c, int s) {
        const int k0 = c * GKS;
        const uint32_t sa = sb + (uint32_t)s * STGb;
        const size_t aoff = (size_t)a_cl * K2v + k0 + a_ks;
        cp_async16(sa + (uint32_t)(a_row*48 + a_ks*2),          g_Shi + aoff, a_sz);
        cp_async16(sa + (uint32_t)(A_PLe*2 + a_row*48 + a_ks*2) - A_PLe*2 + A_PLe*2, g_Slo + aoff, a_sz); // A_lo below
        // (A_lo at byte offset A_PLe*2)
        const size_t boff = (size_t)(k0 + b_kr) * C2v + b_ns;
        cp_async16(sa + (uint32_t)(2*A_PLe*2 + b_kr*272 + b_ns*2),          g_Whi + boff, 16);
        cp_async16(sa + (uint32_t)(2*A_PLe*2 + B_PLe*2 + b_kr*272 + b_ns*2), g_Wlo + boff, 16);
        asm volatile("cp.async.commit_group;" ::: "memory");
    };
    // fix A_lo destination (written clearly):
    auto stage_load2 = [&](int c, int s) {
        const int k0 = c * GKS;
        const uint32_t sa = sb + (uint32_t)s * STGb;
        const size_t aoff = (size_t)a_cl * K2v + k0 + a_ks;
        cp_async16(sa + (uint32_t)(a_row*48 + a_ks*2),               g_Shi + aoff, a_sz);
        cp_async16(sa + (uint32_t)(A_PLe*2 + a_row*48 + a_ks*2),     g_Slo + aoff, a_sz);
        const size_t boff = (size_t)(k0 + b_kr) * C2v + b_ns;
        cp_async16(sa + (uint32_t)(2*A_PLe*2 + b_kr*272 + b_ns*2),           g_Whi + boff, 16);
        cp_async16(sa + (uint32_t)(2*A_PLe*2 + B_PLe*2 + b_kr*272 + b_ns*2), g_Wlo + boff, 16);
        asm volatile("cp.async.commit_group;" ::: "memory");
    };
    (void)stage_load;

    stage_load2(0, 0);

    for (int c = 0; c < GNST; c++) {
        const int s = c & 1;
        if (c + 1 < GNST) {
            stage_load2(c + 1, s ^ 1);
            asm volatile("cp.async.wait_group 1;" ::: "memory");
        } else {
            asm volatile("cp.async.wait_group 0;" ::: "memory");
        }
        __syncthreads();

        const __nv_bfloat16* stg = smb + (size_t)s * STGe;
        wmma::fragment<wmma::matrix_a, 16, 16, 16, __nv_bfloat16, wmma::row_major> fah[2], fal[2];
        #pragma unroll
        for (int i = 0; i < 2; i++) {
            const __nv_bfloat16* p = stg + (wm*32 + i*16)*24;
            wmma::load_matrix_sync(fah[i], p, 24);
            wmma::load_matrix_sync(fal[i], p + A_PLe, 24);
        }
        wmma::fragment<wmma::matrix_b, 16, 16, 16, __nv_bfloat16, wmma::row_major> fbh[4], fbl[4];
        #pragma unroll
        for (int j = 0; j < 4; j++) {
            const __nv_bfloat16* p = stg + 2*A_PLe + wn*64 + j*16;
            wmma::load_matrix_sync(fbh[j], p, 136);
            wmma::load_matrix_sync(fbl[j], p + B_PLe, 136);
        }
        #pragma unroll
        for (int i = 0; i < 2; i++)
            #pragma unroll
            for (int j = 0; j < 4; j++) {
                wmma::mma_sync(acc[i][j], fah[i], fbh[j], acc[i][j]);
                wmma::mma_sync(acc[i][j], fal[i], fbh[j], acc[i][j]);
                wmma::mma_sync(acc[i][j], fah[i], fbl[j], acc[i][j]);
            }
        __syncthreads();
    }

    // epilogue: accum -> smem (fp32) -> bias + ELU -> coalesced store
    float* et = (float*)sm;
    #pragma unroll
    for (int i = 0; i < 2; i++)
        #pragma unroll
        for (int j = 0; j < 4; j++)
            wmma::store_matrix_sync(et + (size_t)(wm*32 + i*16)*EPI_LD + wn*64 + j*16,
                                    acc[i][j], EPI_LD, wmma::mem_row_major);
    __syncthreads();

    const int row = t >> 1, c0 = (t & 1) * 64;
    if (m0 + row < NROW) {
        #pragma unroll
        for (int cf = 0; cf < 16; cf++) {
            float4 v = *(const float4*)(et + (size_t)row*EPI_LD + c0 + cf*4);
            float4 o;
            o.x = elu(v.x + __ldg(&bias2[c0 + cf*4 + 0]));
            o.y = elu(v.y + __ldg(&bias2[c0 + cf*4 + 1]));
            o.z = elu(v.z + __ldg(&bias2[c0 + cf*4 + 2]));
            o.w = elu(v.w + __ldg(&bias2[c0 + cf*4 + 3]));
            *(float4*)(g_h2 + (size_t)(m0 + row)*C2v + c0 + cf*4) = o;
        }
    }
}

// ================= final dense (HBM streaming) =====================
__global__ void __launch_bounds__(256) dense_kernel(
    const float* __restrict__ Wm, const float* __restrict__ Ws)
{
    const int warp = threadIdx.x >> 5, lane = threadIdx.x & 31;
    const int l0 = blockIdx.x * 32 + warp * 4;
    const int ks = blockIdx.y;
    const int k0 = ks * KCHUNK;

    const float* Wp = (l0 < 256) ? (Wm + (size_t)l0 * KDv)
                                 : (Ws + (size_t)(l0 - 256) * KDv);
    const float* f = g_h3;

    float acc[4][8];
    #pragma unroll
    for (int j = 0; j < 4; j++)
        #pragma unroll
        for (int b = 0; b < 8; b++) acc[j][b] = 0.f;

    for (int k = k0 + lane; k < k0 + KCHUNK; k += 32) {
        float fv[8];
        #pragma unroll
        for (int b = 0; b < 8; b++) fv[b] = f[(size_t)b*KDv + k];
        #pragma unroll
        for (int j = 0; j < 4; j++) {
            float wv = Wp[(size_t)j*KDv + k];
            #pragma unroll
            for (int b = 0; b < 8; b++) acc[j][b] += wv * fv[b];
        }
    }

    #pragma unroll
    for (int j = 0; j < 4; j++)
        #pragma unroll
        for (int b = 0; b < 8; b++) {
            float v = acc[j][b];
            #pragma unroll
            for (int off = 16; off > 0; off >>= 1)
                v += __shfl_xor_sync(0xffffffffu, v, off);
            acc[j][b] = v;
        }

    if (lane == 0) {
        #pragma unroll
        for (int j = 0; j < 4; j++)
            #pragma unroll
            for (int b = 0; b < 8; b++)
                g_part[((size_t)ks*Bv + b)*LOUT + l0 + j] = acc[j][b];
    }
}

__global__ void reduce_kernel(const float* __restrict__ bm,
                              const float* __restrict__ bs,
                              float* __restrict__ out)
{
    int e = blockIdx.x * 256 + threadIdx.x;   // 4096
    if (e >= Bv*LOUT) return;
    int b = e >> 9, l = e & 511;
    float acc = (l < 256) ? bm[l] : bs[l - 256];
    #pragma unroll 5
    for (int ks = 0; ks < KSPLIT; ks++)
        acc += g_part[((size_t)ks*Bv + b)*LOUT + l];
    out[e] = acc;
}

// ================= launch =========================================
extern "C" void kernel_launch(void* const* d_in, const int* in_sizes, int n_in,
                              void* d_out, int out_size)
{
    const float* x    = (const float*)d_in[0];
    const int*   nb0  = (const int*)  d_in[1];
    const int*   nb1  = (const int*)  d_in[2];
    const int*   nb2  = (const int*)  d_in[3];
    const int*   nb3  = (const int*)  d_in[4];
    const float* w0   = (const float*)d_in[5];
    const float* bia0 = (const float*)d_in[6];
    const float* ww0  = (const float*)d_in[7];
    const float* pn1  = (const float*)d_in[8];
    const float* w2   = (const float*)d_in[9];
    const float* bia2 = (const float*)d_in[10];
    const float* ww2  = (const float*)d_in[11];
    const float* pn3  = (const float*)d_in[12];
    const float* Wm   = (const float*)d_in[13];
    const float* bm   = (const float*)d_in[14];
    const float* Ws   = (const float*)d_in[15];
    const float* bs   = (const float*)d_in[16];
    float* out = (float*)d_out;

    static bool attr_done = false;
    if (!attr_done) {
        cudaFuncSetAttribute(gemm_wmma_kernel,
                             cudaFuncAttributeMaxDynamicSharedMemorySize, GEMM_SMEM);
        attr_done = true;
    }

    conv0_kernel<<<P0v/CPTS, 512>>>(x, nb0, w0, bia0, ww0);
    pool_kernel<C1v, P0v, P1v, 0><<<P1v, C1v*Bv>>>(nb1, pn1);
    conv2s_kernel<<<P1v, 512>>>(nb2, ww2);
    wmat_split_kernel<<<(K2v*C2v + 255)/256, 256>>>(w2);
    gemm_wmma_kernel<<<(NROW + 127)/128, 256, GEMM_SMEM>>>(bia2);
    pool_kernel<C2v, P1v, P2v, 1><<<P2v, C2v*Bv>>>(nb3, pn3);
    dense_kernel<<<dim3(16, KSPLIT), 256>>>(Wm, Ws);
    reduce_kernel<<<(Bv*LOUT + 255)/256, 256>>>(bm, bs, out);
}

// round 8
// speedup vs baseline: 1.4301x; 1.0723x over previous
#include <cuda_runtime.h>
#include <cuda_bf16.h>
#include <mma.h>
#include <cstdint>

using namespace nvcuda;

// ---------------- problem constants ----------------
#define Bv    8
#define P0v   20000
#define P1v   5000
#define P2v   1250
#define Mv    10
#define Wv    9
#define C0v   3
#define C1v   64
#define C2v   128
#define K2v   576            // W*C1
#define NROW  (Bv*P1v)       // 40000 GEMM rows
#define KDv   (P2v*C2v)      // 160000
#define LOUT  512            // 2*LATENT
#define KSPLIT 25
#define KCHUNK (KDv/KSPLIT)  // 6400

// ---------------- device scratch ----------------
__device__ __align__(128) float g_h0[Bv*(size_t)P0v*C1v];
__device__ __align__(128) float g_h1[Bv*(size_t)P1v*C1v];
__device__ __align__(128) float g_h2[Bv*(size_t)P1v*C2v];
__device__ __align__(128) float g_h3[Bv*(size_t)P2v*C2v];
__device__ __align__(128) __nv_bfloat16 g_Shi[(size_t)NROW*K2v];
__device__ __align__(128) __nv_bfloat16 g_Slo[(size_t)NROW*K2v];
__device__ __align__(128) __nv_bfloat16 g_Whi[K2v*C2v];
__device__ __align__(128) __nv_bfloat16 g_Wlo[K2v*C2v];
__device__ __align__(128) float g_part[KSPLIT*Bv*LOUT];

__device__ __forceinline__ float elu(float x) {
    return x > 0.f ? x : expm1f(x);
}
__device__ __forceinline__ uint32_t smem_to_u32(const void* p) {
    uint32_t a;
    asm("{ .reg .u64 tmp; cvta.to.shared.u64 tmp, %1; cvt.u32.u64 %0, tmp; }"
        : "=r"(a) : "l"(p));
    return a;
}
__device__ __forceinline__ void cp_async16(uint32_t d, const void* s, int srcsize) {
    asm volatile("cp.async.ca.shared.global [%0], [%1], 16, %2;"
                 :: "r"(d), "l"(s), "r"(srcsize) : "memory");
}

// ================= kernel 1: conv0 + ELU (8 points per block) ======
#define CPTS 8
__global__ void __launch_bounds__(512) conv0_kernel(
    const float* __restrict__ x, const int* __restrict__ nb0,
    const float* __restrict__ w0, const float* __restrict__ bias0,
    const float* __restrict__ ww0)
{
    __shared__ float Wt[27][C1v];
    __shared__ float wws[CPTS][Mv*Wv];
    __shared__ int   nbs[CPTS][Mv];
    __shared__ float xg[CPTS][Bv][32];
    __shared__ float s[CPTS][Bv][28];

    const int p0 = blockIdx.x * CPTS;
    const int t  = threadIdx.x;

    for (int e = t; e < 27*C1v; e += 512) {
        int k = e >> 6, o = e & 63;
        Wt[k][o] = w0[(k/3)*192 + o*3 + (k%3)];
    }
    if (t < CPTS*Mv) nbs[t/Mv][t%Mv] = nb0[p0*Mv + t];
    for (int e = t; e < CPTS*Mv*Wv; e += 512)
        wws[e/(Mv*Wv)][e%(Mv*Wv)] = ww0[p0*Mv*Wv + e];
    __syncthreads();

    for (int e = t; e < CPTS*Bv*Mv*C0v; e += 512) {
        int j = e / 240, r = e % 240;
        int b = r / 30, q = r % 30;
        int m = q / 3, i = q % 3;
        int idx = nbs[j][m];
        xg[j][b][q] = (idx < P0v) ? x[((size_t)b*P0v + idx)*C0v + i] : 0.f;
    }
    __syncthreads();

    for (int e = t; e < CPTS*Bv*27; e += 512) {
        int j = e / 216, r = e % 216;
        int b = r / 27, k = r % 27;
        int w = k / 3, i = k % 3;
        float acc = 0.f;
        #pragma unroll
        for (int m = 0; m < Mv; m++) acc += wws[j][m*Wv + w] * xg[j][b][m*3 + i];
        s[j][b][k] = acc;
    }
    __syncthreads();

    const int tx = t & 63, ty = t >> 6;
    const float bia = bias0[tx];
    #pragma unroll
    for (int j = 0; j < CPTS; j++) {
        float acc = bia;
        #pragma unroll
        for (int k = 0; k < 27; k++) acc += s[j][ty][k] * Wt[k][tx];
        g_h0[((size_t)ty*P0v + p0 + j)*C1v + tx] = elu(acc);
    }
}

// ================= pooling (pool1 / pool3) + ELU ===================
template<int C, int Pin, int Pout, int STAGE>
__global__ void pool_kernel(const int* __restrict__ nb,
                            const float* __restrict__ pnb)
{
    const float* __restrict__ hin  = (STAGE == 0) ? g_h0 : g_h2;
    float*       __restrict__ hout = (STAGE == 0) ? g_h1 : g_h3;

    __shared__ int   nbs[Mv];
    __shared__ float wt[Mv];
    const int p = blockIdx.x;
    const int t = threadIdx.x;
    if (t < Mv) {
        int idx = nb[p*Mv + t];
        nbs[t] = idx;
        wt[t]  = (idx < Pin) ? fabsf(pnb[p*Mv + t]) : 0.f;
    }
    __syncthreads();
    float denom = 1e-8f;
    #pragma unroll
    for (int m = 0; m < Mv; m++) denom += wt[m];

    const int c = t % C, b = t / C;
    float acc = 0.f;
    #pragma unroll
    for (int m = 0; m < Mv; m++) {
        int idx = nbs[m];
        if (idx < Pin) acc += wt[m] * hin[((size_t)b*Pin + idx)*C + c];
    }
    acc /= denom;
    hout[((size_t)b*Pout + p)*C + c] = elu(acc);
}

// ====== conv2 stage A: S -> bf16 hi/lo planes; + fused weight split ====
__global__ void __launch_bounds__(512) conv2s_kernel(
    const int* __restrict__ nb2, const float* __restrict__ ww2,
    const float* __restrict__ w2)
{
    // fused wmat split: blocks 0..143 handle 512 elements each (144*512 = 73728)
    if (blockIdx.x < 144) {
        int e = blockIdx.x * 512 + threadIdx.x;
        int k = e >> 7, n = e & 127;
        float v = w2[(k >> 6)*(C2v*C1v) + n*C1v + (k & 63)];
        __nv_bfloat16 hi = __float2bfloat16(v);
        g_Whi[e] = hi;
        g_Wlo[e] = __float2bfloat16(v - __bfloat162float(hi));
    }

    __shared__ int   nbs[Mv];
    __shared__ float wws[Mv*Wv];
    const int p = blockIdx.x;
    const int t = threadIdx.x;
    if (t < Mv)    nbs[t] = nb2[p*Mv + t];
    if (t < Mv*Wv) wws[t] = ww2[p*Mv*Wv + t];
    __syncthreads();

    const int i = t & 63, b = t >> 6;
    float acc[Wv];
    #pragma unroll
    for (int w = 0; w < Wv; w++) acc[w] = 0.f;
    #pragma unroll
    for (int m = 0; m < Mv; m++) {
        int idx = nbs[m];
        if (idx < P1v) {
            float v = g_h1[((size_t)b*P1v + idx)*C1v + i];
            #pragma unroll
            for (int w = 0; w < Wv; w++) acc[w] += wws[m*Wv + w] * v;
        }
    }
    const size_t r = (size_t)b*P1v + p;
    #pragma unroll
    for (int w = 0; w < Wv; w++) {
        size_t idx = (r*Wv + w)*C1v + i;
        __nv_bfloat16 hi = __float2bfloat16(acc[w]);
        g_Shi[idx] = hi;
        g_Slo[idx] = __float2bfloat16(acc[w] - __bfloat162float(hi));
    }
}

// ================= wmma bf16x3 GEMM: h2 = ELU(S @ W + bias2) =======
// CTA 128x128, 256 thr (warps 4x2, warp tile 32x64), k-step 32,
// double-buffered cp.async, ONE __syncthreads per k-step.
// A ldm=40, B ldm=136 (both LDSM conflict-free).
#define GKS    32
#define GNST   (K2v/GKS)        // 18
#define A_LD   40
#define B_LD   136
#define A_PLe  (128*A_LD)       // 5120 elems per plane
#define B_PLe  (GKS*B_LD)       // 4352 elems per plane
#define STGe   (2*A_PLe + 2*B_PLe)   // 18944 elems
#define STGb   (2*STGe)              // 37888 bytes per stage
#define EPI_LD 132
#define GEMM_SMEM (2*STGb > 128*EPI_LD*4 ? 2*STGb : 128*EPI_LD*4)  // 75776

__global__ void __launch_bounds__(256) gemm_wmma_kernel(const float* __restrict__ bias2)
{
    extern __shared__ char sm[];
    __nv_bfloat16* smb = (__nv_bfloat16*)sm;
    const uint32_t sb = smem_to_u32(sm);
    const int t = threadIdx.x;
    const int warp = t >> 5;
    const int wm = warp & 3, wn = warp >> 2;    // 4 x 2
    const int m0 = blockIdx.x * 128;

    // loader mapping: A 128 rows x 32 k (2 x 16B per thread per plane)
    const int a_row = t >> 1, a_ks = (t & 1) * 8;
    // B 32 k-rows x 128 n (2 x 16B per thread per plane)
    const int b_kr  = t >> 4, b_ns = (t & 15) * 8;
    const int g_arow = m0 + a_row;
    const int a_sz  = (g_arow < NROW) ? 16 : 0;
    const int a_cl  = (g_arow < NROW) ? g_arow : 0;

    wmma::fragment<wmma::accumulator, 16, 16, 16, float> acc[2][4];
    #pragma unroll
    for (int i = 0; i < 2; i++)
        #pragma unroll
        for (int j = 0; j < 4; j++) wmma::fill_fragment(acc[i][j], 0.f);

    auto stage_load = [&](int c, int s) {
        const int k0 = c * GKS;
        const uint32_t sa = sb + (uint32_t)s * STGb;
        #pragma unroll
        for (int kk = 0; kk < 2; kk++) {
            const int ks = a_ks + kk*16;
            const size_t aoff = (size_t)a_cl * K2v + k0 + ks;
            cp_async16(sa + (uint32_t)(a_row*A_LD + ks)*2,            g_Shi + aoff, a_sz);
            cp_async16(sa + (uint32_t)(A_PLe + a_row*A_LD + ks)*2,    g_Slo + aoff, a_sz);
        }
        #pragma unroll
        for (int kk = 0; kk < 2; kk++) {
            const int kr = b_kr + kk*16;
            const size_t boff = (size_t)(k0 + kr) * C2v + b_ns;
            cp_async16(sa + (uint32_t)(2*A_PLe + kr*B_LD + b_ns)*2,          g_Whi + boff, 16);
            cp_async16(sa + (uint32_t)(2*A_PLe + B_PLe + kr*B_LD + b_ns)*2,  g_Wlo + boff, 16);
        }
        asm volatile("cp.async.commit_group;" ::: "memory");
    };

    stage_load(0, 0);

    for (int c = 0; c < GNST; c++) {
        const int s = c & 1;
        asm volatile("cp.async.wait_group 0;" ::: "memory");
        __syncthreads();
        if (c + 1 < GNST) stage_load(c + 1, s ^ 1);

        const __nv_bfloat16* stg = smb + (size_t)s * STGe;
        #pragma unroll
        for (int kk = 0; kk < 2; kk++) {
            wmma::fragment<wmma::matrix_a, 16, 16, 16, __nv_bfloat16, wmma::row_major> fah[2], fal[2];
            #pragma unroll
            for (int i = 0; i < 2; i++) {
                const __nv_bfloat16* p = stg + (size_t)(wm*32 + i*16)*A_LD + kk*16;
                wmma::load_matrix_sync(fah[i], p, A_LD);
                wmma::load_matrix_sync(fal[i], p + A_PLe, A_LD);
            }
            wmma::fragment<wmma::matrix_b, 16, 16, 16, __nv_bfloat16, wmma::row_major> fbh[4], fbl[4];
            #pragma unroll
            for (int j = 0; j < 4; j++) {
                const __nv_bfloat16* p = stg + 2*A_PLe + (size_t)(kk*16)*B_LD + wn*64 + j*16;
                wmma::load_matrix_sync(fbh[j], p, B_LD);
                wmma::load_matrix_sync(fbl[j], p + B_PLe, B_LD);
            }
            #pragma unroll
            for (int i = 0; i < 2; i++)
                #pragma unroll
                for (int j = 0; j < 4; j++) {
                    wmma::mma_sync(acc[i][j], fah[i], fbh[j], acc[i][j]);
                    wmma::mma_sync(acc[i][j], fal[i], fbh[j], acc[i][j]);
                    wmma::mma_sync(acc[i][j], fah[i], fbl[j], acc[i][j]);
                }
        }
    }
    __syncthreads();   // protect smem reuse (epilogue overlaps stage buffers)

    // epilogue: accum -> smem fp32 -> bias + ELU -> coalesced store
    float* et = (float*)sm;
    #pragma unroll
    for (int i = 0; i < 2; i++)
        #pragma unroll
        for (int j = 0; j < 4; j++)
            wmma::store_matrix_sync(et + (size_t)(wm*32 + i*16)*EPI_LD + wn*64 + j*16,
                                    acc[i][j], EPI_LD, wmma::mem_row_major);
    __syncthreads();

    const int row = t >> 1, c0 = (t & 1) * 64;
    if (m0 + row < NROW) {
        #pragma unroll
        for (int cf = 0; cf < 16; cf++) {
            float4 v = *(const float4*)(et + (size_t)row*EPI_LD + c0 + cf*4);
            float4 o;
            o.x = elu(v.x + __ldg(&bias2[c0 + cf*4 + 0]));
            o.y = elu(v.y + __ldg(&bias2[c0 + cf*4 + 1]));
            o.z = elu(v.z + __ldg(&bias2[c0 + cf*4 + 2]));
            o.w = elu(v.w + __ldg(&bias2[c0 + cf*4 + 3]));
            *(float4*)(g_h2 + (size_t)(m0 + row)*C2v + c0 + cf*4) = o;
        }
    }
}

// ================= final dense (HBM streaming, float4) =============
__global__ void __launch_bounds__(256) dense_kernel(
    const float* __restrict__ Wm, const float* __restrict__ Ws)
{
    const int warp = threadIdx.x >> 5, lane = threadIdx.x & 31;
    const int l0 = blockIdx.x * 32 + warp * 4;
    const int ks = blockIdx.y;
    const int k0 = ks * KCHUNK;

    const float* Wp = (l0 < 256) ? (Wm + (size_t)l0 * KDv)
                                 : (Ws + (size_t)(l0 - 256) * KDv);
    const float* f = g_h3;

    float acc[4][8];
    #pragma unroll
    for (int j = 0; j < 4; j++)
        #pragma unroll
        for (int b = 0; b < 8; b++) acc[j][b] = 0.f;

    for (int k = k0 + lane*4; k < k0 + KCHUNK; k += 128) {
        float4 fv[8];
        #pragma unroll
        for (int b = 0; b < 8; b++) fv[b] = *(const float4*)(f + (size_t)b*KDv + k);
        #pragma unroll
        for (int j = 0; j < 4; j++) {
            float4 wv = *(const float4*)(Wp + (size_t)j*KDv + k);
            #pragma unroll
            for (int b = 0; b < 8; b++) {
                acc[j][b] += wv.x * fv[b].x + wv.y * fv[b].y
                           + wv.z * fv[b].z + wv.w * fv[b].w;
            }
        }
    }

    #pragma unroll
    for (int j = 0; j < 4; j++)
        #pragma unroll
        for (int b = 0; b < 8; b++) {
            float v = acc[j][b];
            #pragma unroll
            for (int off = 16; off > 0; off >>= 1)
                v += __shfl_xor_sync(0xffffffffu, v, off);
            acc[j][b] = v;
        }

    if (lane == 0) {
        #pragma unroll
        for (int j = 0; j < 4; j++)
            #pragma unroll
            for (int b = 0; b < 8; b++)
                g_part[((size_t)ks*Bv + b)*LOUT + l0 + j] = acc[j][b];
    }
}

__global__ void reduce_kernel(const float* __restrict__ bm,
                              const float* __restrict__ bs,
                              float* __restrict__ out)
{
    int e = blockIdx.x * 256 + threadIdx.x;
    if (e >= Bv*LOUT) return;
    int b = e >> 9, l = e & 511;
    float acc = (l < 256) ? bm[l] : bs[l - 256];
    #pragma unroll 5
    for (int ks = 0; ks < KSPLIT; ks++)
        acc += g_part[((size_t)ks*Bv + b)*LOUT + l];
    out[e] = acc;
}

// ================= launch =========================================
extern "C" void kernel_launch(void* const* d_in, const int* in_sizes, int n_in,
                              void* d_out, int out_size)
{
    const float* x    = (const float*)d_in[0];
    const int*   nb0  = (const int*)  d_in[1];
    const int*   nb1  = (const int*)  d_in[2];
    const int*   nb2  = (const int*)  d_in[3];
    const int*   nb3  = (const int*)  d_in[4];
    const float* w0   = (const float*)d_in[5];
    const float* bia0 = (const float*)d_in[6];
    const float* ww0  = (const float*)d_in[7];
    const float* pn1  = (const float*)d_in[8];
    const float* w2   = (const float*)d_in[9];
    const float* bia2 = (const float*)d_in[10];
    const float* ww2  = (const float*)d_in[11];
    const float* pn3  = (const float*)d_in[12];
    const float* Wm   = (const float*)d_in[13];
    const float* bm   = (const float*)d_in[14];
    const float* Ws   = (const float*)d_in[15];
    const float* bs   = (const float*)d_in[16];
    float* out = (float*)d_out;

    cudaFuncSetAttribute(gemm_wmma_kernel,
                         cudaFuncAttributeMaxDynamicSharedMemorySize, GEMM_SMEM);

    conv0_kernel<<<P0v/CPTS, 512>>>(x, nb0, w0, bia0, ww0);
    pool_kernel<C1v, P0v, P1v, 0><<<P1v, C1v*Bv>>>(nb1, pn1);
    conv2s_kernel<<<P1v, 512>>>(nb2, ww2, w2);
    gemm_wmma_kernel<<<(NROW + 127)/128, 256, GEMM_SMEM>>>(bia2);
    pool_kernel<C2v, P1v, P2v, 1><<<P2v, C2v*Bv>>>(nb3, pn3);
    dense_kernel<<<dim3(16, KSPLIT), 256>>>(Wm, Ws);
    reduce_kernel<<<(Bv*LOUT + 255)/256, 256>>>(bm, bs, out);
}

// round 9
// speedup vs baseline: 1.4949x; 1.0453x over previous
#include <cuda_runtime.h>
#include <cuda_bf16.h>
#include <mma.h>
#include <cstdint>

using namespace nvcuda;

// ---------------- problem constants ----------------
#define Bv    8
#define P0v   20000
#define P1v   5000
#define P2v   1250
#define Mv    10
#define Wv    9
#define C0v   3
#define C1v   64
#define C2v   128
#define K2v   576            // W*C1
#define NROW  (Bv*P1v)       // 40000 GEMM rows
#define KDv   (P2v*C2v)      // 160000
#define LOUT  512            // 2*LATENT
#define KSPLIT 25
#define KCHUNK (KDv/KSPLIT)  // 6400

// ---------------- device scratch ----------------
__device__ __align__(128) float g_h0[Bv*(size_t)P0v*C1v];
__device__ __align__(128) float g_h1[Bv*(size_t)P1v*C1v];
__device__ __align__(128) float g_h2[Bv*(size_t)P1v*C2v];
__device__ __align__(128) float g_h3[Bv*(size_t)P2v*C2v];
__device__ __align__(128) __nv_bfloat16 g_Shi[(size_t)NROW*K2v];
__device__ __align__(128) __nv_bfloat16 g_Slo[(size_t)NROW*K2v];
__device__ __align__(128) __nv_bfloat16 g_Whi[K2v*C2v];
__device__ __align__(128) __nv_bfloat16 g_Wlo[K2v*C2v];
__device__ __align__(128) float g_part[KSPLIT*Bv*LOUT];

__device__ __forceinline__ float elu(float x) {
    return x > 0.f ? x : expm1f(x);
}
__device__ __forceinline__ uint32_t smem_to_u32(const void* p) {
    uint32_t a;
    asm("{ .reg .u64 tmp; cvta.to.shared.u64 tmp, %1; cvt.u32.u64 %0, tmp; }"
        : "=r"(a) : "l"(p));
    return a;
}
__device__ __forceinline__ void cp_async16(uint32_t d, const void* s, int srcsize) {
    asm volatile("cp.async.ca.shared.global [%0], [%1], 16, %2;"
                 :: "r"(d), "l"(s), "r"(srcsize) : "memory");
}

// ================= kernel 1: conv0 + ELU (8 points per block) ======
#define CPTS 8
__global__ void __launch_bounds__(512) conv0_kernel(
    const float* __restrict__ x, const int* __restrict__ nb0,
    const float* __restrict__ w0, const float* __restrict__ bias0,
    const float* __restrict__ ww0)
{
    __shared__ float Wt[27][C1v];
    __shared__ float wws[CPTS][Mv*Wv];
    __shared__ int   nbs[CPTS][Mv];
    __shared__ float xg[CPTS][Bv][32];
    __shared__ float s[CPTS][Bv][28];

    const int p0 = blockIdx.x * CPTS;
    const int t  = threadIdx.x;

    for (int e = t; e < 27*C1v; e += 512) {
        int k = e >> 6, o = e & 63;
        Wt[k][o] = w0[(k/3)*192 + o*3 + (k%3)];
    }
    if (t < CPTS*Mv) nbs[t/Mv][t%Mv] = nb0[p0*Mv + t];
    for (int e = t; e < CPTS*Mv*Wv; e += 512)
        wws[e/(Mv*Wv)][e%(Mv*Wv)] = ww0[p0*Mv*Wv + e];
    __syncthreads();

    for (int e = t; e < CPTS*Bv*Mv*C0v; e += 512) {
        int j = e / 240, r = e % 240;
        int b = r / 30, q = r % 30;
        int m = q / 3, i = q % 3;
        int idx = nbs[j][m];
        xg[j][b][q] = (idx < P0v) ? x[((size_t)b*P0v + idx)*C0v + i] : 0.f;
    }
    __syncthreads();

    for (int e = t; e < CPTS*Bv*27; e += 512) {
        int j = e / 216, r = e % 216;
        int b = r / 27, k = r % 27;
        int w = k / 3, i = k % 3;
        float acc = 0.f;
        #pragma unroll
        for (int m = 0; m < Mv; m++) acc += wws[j][m*Wv + w] * xg[j][b][m*3 + i];
        s[j][b][k] = acc;
    }
    __syncthreads();

    const int tx = t & 63, ty = t >> 6;
    const float bia = bias0[tx];
    #pragma unroll
    for (int j = 0; j < CPTS; j++) {
        float acc = bia;
        #pragma unroll
        for (int k = 0; k < 27; k++) acc += s[j][ty][k] * Wt[k][tx];
        g_h0[((size_t)ty*P0v + p0 + j)*C1v + tx] = elu(acc);
    }
}

// ================= pooling (pool1 / pool3) + ELU ===================
template<int C, int Pin, int Pout, int STAGE>
__global__ void pool_kernel(const int* __restrict__ nb,
                            const float* __restrict__ pnb)
{
    const float* __restrict__ hin  = (STAGE == 0) ? g_h0 : g_h2;
    float*       __restrict__ hout = (STAGE == 0) ? g_h1 : g_h3;

    __shared__ int   nbs[Mv];
    __shared__ float wt[Mv];
    const int p = blockIdx.x;
    const int t = threadIdx.x;
    if (t < Mv) {
        int idx = nb[p*Mv + t];
        nbs[t] = idx;
        wt[t]  = (idx < Pin) ? fabsf(pnb[p*Mv + t]) : 0.f;
    }
    __syncthreads();
    float denom = 1e-8f;
    #pragma unroll
    for (int m = 0; m < Mv; m++) denom += wt[m];

    const int c = t % C, b = t / C;
    float acc = 0.f;
    #pragma unroll
    for (int m = 0; m < Mv; m++) {
        int idx = nbs[m];
        if (idx < Pin) acc += wt[m] * hin[((size_t)b*Pin + idx)*C + c];
    }
    acc /= denom;
    hout[((size_t)b*Pout + p)*C + c] = elu(acc);
}

// ====== conv2 stage A: S -> bf16 hi/lo planes; + fused weight split ====
__global__ void __launch_bounds__(512) conv2s_kernel(
    const int* __restrict__ nb2, const float* __restrict__ ww2,
    const float* __restrict__ w2)
{
    // fused wmat split: blocks 0..143 handle 512 elements each
    if (blockIdx.x < 144) {
        int e = blockIdx.x * 512 + threadIdx.x;
        int k = e >> 7, n = e & 127;
        float v = w2[(k >> 6)*(C2v*C1v) + n*C1v + (k & 63)];
        __nv_bfloat16 hi = __float2bfloat16(v);
        g_Whi[e] = hi;
        g_Wlo[e] = __float2bfloat16(v - __bfloat162float(hi));
    }

    __shared__ int   nbs[Mv];
    __shared__ float wws[Mv*Wv];
    const int p = blockIdx.x;
    const int t = threadIdx.x;
    if (t < Mv)    nbs[t] = nb2[p*Mv + t];
    if (t < Mv*Wv) wws[t] = ww2[p*Mv*Wv + t];
    __syncthreads();

    const int i = t & 63, b = t >> 6;
    float acc[Wv];
    #pragma unroll
    for (int w = 0; w < Wv; w++) acc[w] = 0.f;
    #pragma unroll
    for (int m = 0; m < Mv; m++) {
        int idx = nbs[m];
        if (idx < P1v) {
            float v = g_h1[((size_t)b*P1v + idx)*C1v + i];
            #pragma unroll
            for (int w = 0; w < Wv; w++) acc[w] += wws[m*Wv + w] * v;
        }
    }
    const size_t r = (size_t)b*P1v + p;
    #pragma unroll
    for (int w = 0; w < Wv; w++) {
        size_t idx = (r*Wv + w)*C1v + i;
        __nv_bfloat16 hi = __float2bfloat16(acc[w]);
        g_Shi[idx] = hi;
        g_Slo[idx] = __float2bfloat16(acc[w] - __bfloat162float(hi));
    }
}

// ================= wmma bf16x3 GEMM: h2 = ELU(S @ W + bias2) =======
// CTA 128x128, 512 thr (warps 4x4, warp tile 32x32), k-step 32,
// 3-stage cp.async pipeline, one __syncthreads per k-step.
// A ldm=40, B ldm=136 (both LDSM conflict-free).
#define GKS    32
#define GNST   (K2v/GKS)        // 18
#define A_LD   40
#define B_LD   136
#define A_PLe  (128*A_LD)       // 5120 elems per plane
#define B_PLe  (GKS*B_LD)       // 4352 elems per plane
#define STGe   (2*A_PLe + 2*B_PLe)   // 18944 elems
#define STGb   (2*STGe)              // 37888 bytes per stage
#define NSTG   3
#define EPI_LD 132
#define EPIB   (128*EPI_LD*4)        // 67584
#define GEMM_SMEM (NSTG*STGb)        // 113664

__global__ void __launch_bounds__(512) gemm_wmma_kernel(const float* __restrict__ bias2)
{
    extern __shared__ char sm[];
    __nv_bfloat16* smb = (__nv_bfloat16*)sm;
    const uint32_t sb = smem_to_u32(sm);
    const int t = threadIdx.x;
    const int warp = t >> 5;
    const int wm = warp & 3, wn = warp >> 2;    // 4 x 4
    const int m0 = blockIdx.x * 128;

    // loader mapping: A 128 rows x 32 k, 1 x 16B per thread per plane
    const int a_row = t >> 2, a_ks = (t & 3) * 8;
    // B 32 k-rows x 128 n, 1 x 16B per thread per plane
    const int b_kr  = t >> 4, b_ns = (t & 15) * 8;
    const int g_arow = m0 + a_row;
    const int a_sz  = (g_arow < NROW) ? 16 : 0;
    const int a_cl  = (g_arow < NROW) ? g_arow : 0;

    wmma::fragment<wmma::accumulator, 16, 16, 16, float> acc[2][2];
    #pragma unroll
    for (int i = 0; i < 2; i++)
        #pragma unroll
        for (int j = 0; j < 2; j++) wmma::fill_fragment(acc[i][j], 0.f);

    auto stage_load = [&](int c, int s) {
        const int k0 = c * GKS;
        const uint32_t sa = sb + (uint32_t)s * STGb;
        const size_t aoff = (size_t)a_cl * K2v + k0 + a_ks;
        cp_async16(sa + (uint32_t)(a_row*A_LD + a_ks)*2,          g_Shi + aoff, a_sz);
        cp_async16(sa + (uint32_t)(A_PLe + a_row*A_LD + a_ks)*2,  g_Slo + aoff, a_sz);
        const size_t boff = (size_t)(k0 + b_kr) * C2v + b_ns;
        cp_async16(sa + (uint32_t)(2*A_PLe + b_kr*B_LD + b_ns)*2,         g_Whi + boff, 16);
        cp_async16(sa + (uint32_t)(2*A_PLe + B_PLe + b_kr*B_LD + b_ns)*2, g_Wlo + boff, 16);
        asm volatile("cp.async.commit_group;" ::: "memory");
    };

    stage_load(0, 0);
    stage_load(1, 1);

    for (int c = 0; c < GNST; c++) {
        const int s = c % NSTG;
        if (c + 1 < GNST) {
            asm volatile("cp.async.wait_group 1;" ::: "memory");
        } else {
            asm volatile("cp.async.wait_group 0;" ::: "memory");
        }
        __syncthreads();
        if (c + 2 < GNST) stage_load(c + 2, (c + 2) % NSTG);

        const __nv_bfloat16* stg = smb + (size_t)s * STGe;
        #pragma unroll
        for (int kk = 0; kk < 2; kk++) {
            wmma::fragment<wmma::matrix_a, 16, 16, 16, __nv_bfloat16, wmma::row_major> fah[2], fal[2];
            #pragma unroll
            for (int i = 0; i < 2; i++) {
                const __nv_bfloat16* p = stg + (size_t)(wm*32 + i*16)*A_LD + kk*16;
                wmma::load_matrix_sync(fah[i], p, A_LD);
                wmma::load_matrix_sync(fal[i], p + A_PLe, A_LD);
            }
            wmma::fragment<wmma::matrix_b, 16, 16, 16, __nv_bfloat16, wmma::row_major> fbh[2], fbl[2];
            #pragma unroll
            for (int j = 0; j < 2; j++) {
                const __nv_bfloat16* p = stg + 2*A_PLe + (size_t)(kk*16)*B_LD + wn*32 + j*16;
                wmma::load_matrix_sync(fbh[j], p, B_LD);
                wmma::load_matrix_sync(fbl[j], p + B_PLe, B_LD);
            }
            #pragma unroll
            for (int i = 0; i < 2; i++)
                #pragma unroll
                for (int j = 0; j < 2; j++) {
                    wmma::mma_sync(acc[i][j], fah[i], fbh[j], acc[i][j]);
                    wmma::mma_sync(acc[i][j], fal[i], fbh[j], acc[i][j]);
                    wmma::mma_sync(acc[i][j], fah[i], fbl[j], acc[i][j]);
                }
        }
    }
    __syncthreads();   // protect smem reuse (epilogue overlaps stage buffers)

    // epilogue: accum -> smem fp32 -> bias + ELU -> coalesced store
    float* et = (float*)sm;
    #pragma unroll
    for (int i = 0; i < 2; i++)
        #pragma unroll
        for (int j = 0; j < 2; j++)
            wmma::store_matrix_sync(et + (size_t)(wm*32 + i*16)*EPI_LD + wn*32 + j*16,
                                    acc[i][j], EPI_LD, wmma::mem_row_major);
    __syncthreads();

    const int row = t >> 2, c0 = (t & 3) * 32;
    if (m0 + row < NROW) {
        #pragma unroll
        for (int cf = 0; cf < 8; cf++) {
            float4 v = *(const float4*)(et + (size_t)row*EPI_LD + c0 + cf*4);
            float4 o;
            o.x = elu(v.x + __ldg(&bias2[c0 + cf*4 + 0]));
            o.y = elu(v.y + __ldg(&bias2[c0 + cf*4 + 1]));
            o.z = elu(v.z + __ldg(&bias2[c0 + cf*4 + 2]));
            o.w = elu(v.w + __ldg(&bias2[c0 + cf*4 + 3]));
            *(float4*)(g_h2 + (size_t)(m0 + row)*C2v + c0 + cf*4) = o;
        }
    }
}

// ================= final dense (HBM streaming, float4) =============
__global__ void __launch_bounds__(256) dense_kernel(
    const float* __restrict__ Wm, const float* __restrict__ Ws)
{
    const int warp = threadIdx.x >> 5, lane = threadIdx.x & 31;
    const int l0 = blockIdx.x * 32 + warp * 4;
    const int ks = blockIdx.y;
    const int k0 = ks * KCHUNK;

    const float* Wp = (l0 < 256) ? (Wm + (size_t)l0 * KDv)
                                 : (Ws + (size_t)(l0 - 256) * KDv);
    const float* f = g_h3;

    float acc[4][8];
    #pragma unroll
    for (int j = 0; j < 4; j++)
        #pragma unroll
        for (int b = 0; b < 8; b++) acc[j][b] = 0.f;

    for (int k = k0 + lane*4; k < k0 + KCHUNK; k += 128) {
        float4 fv[8];
        #pragma unroll
        for (int b = 0; b < 8; b++) fv[b] = *(const float4*)(f + (size_t)b*KDv + k);
        #pragma unroll
        for (int j = 0; j < 4; j++) {
            float4 wv = *(const float4*)(Wp + (size_t)j*KDv + k);
            #pragma unroll
            for (int b = 0; b < 8; b++) {
                acc[j][b] += wv.x * fv[b].x + wv.y * fv[b].y
                           + wv.z * fv[b].z + wv.w * fv[b].w;
            }
        }
    }

    #pragma unroll
    for (int j = 0; j < 4; j++)
        #pragma unroll
        for (int b = 0; b < 8; b++) {
            float v = acc[j][b];
            #pragma unroll
            for (int off = 16; off > 0; off >>= 1)
                v += __shfl_xor_sync(0xffffffffu, v, off);
            acc[j][b] = v;
        }

    if (lane == 0) {
        #pragma unroll
        for (int j = 0; j < 4; j++)
            #pragma unroll
            for (int b = 0; b < 8; b++)
                g_part[((size_t)ks*Bv + b)*LOUT + l0 + j] = acc[j][b];
    }
}

__global__ void reduce_kernel(const float* __restrict__ bm,
                              const float* __restrict__ bs,
                              float* __restrict__ out)
{
    int e = blockIdx.x * 256 + threadIdx.x;
    if (e >= Bv*LOUT) return;
    int b = e >> 9, l = e & 511;
    float acc = (l < 256) ? bm[l] : bs[l - 256];
    #pragma unroll 5
    for (int ks = 0; ks < KSPLIT; ks++)
        acc += g_part[((size_t)ks*Bv + b)*LOUT + l];
    out[e] = acc;
}

// ================= launch =========================================
extern "C" void kernel_launch(void* const* d_in, const int* in_sizes, int n_in,
                              void* d_out, int out_size)
{
    const float* x    = (const float*)d_in[0];
    const int*   nb0  = (const int*)  d_in[1];
    const int*   nb1  = (const int*)  d_in[2];
    const int*   nb2  = (const int*)  d_in[3];
    const int*   nb3  = (const int*)  d_in[4];
    const float* w0   = (const float*)d_in[5];
    const float* bia0 = (const float*)d_in[6];
    const float* ww0  = (const float*)d_in[7];
    const float* pn1  = (const float*)d_in[8];
    const float* w2   = (const float*)d_in[9];
    const float* bia2 = (const float*)d_in[10];
    const float* ww2  = (const float*)d_in[11];
    const float* pn3  = (const float*)d_in[12];
    const float* Wm   = (const float*)d_in[13];
    const float* bm   = (const float*)d_in[14];
    const float* Ws   = (const float*)d_in[15];
    const float* bs   = (const float*)d_in[16];
    float* out = (float*)d_out;

    cudaFuncSetAttribute(gemm_wmma_kernel,
                         cudaFuncAttributeMaxDynamicSharedMemorySize, GEMM_SMEM);

    conv0_kernel<<<P0v/CPTS, 512>>>(x, nb0, w0, bia0, ww0);
    pool_kernel<C1v, P0v, P1v, 0><<<P1v, C1v*Bv>>>(nb1, pn1);
    conv2s_kernel<<<P1v, 512>>>(nb2, ww2, w2);
    gemm_wmma_kernel<<<(NROW + 127)/128, 512, GEMM_SMEM>>>(bia2);
    pool_kernel<C2v, P1v, P2v, 1><<<P2v, C2v*Bv>>>(nb3, pn3);
    dense_kernel<<<dim3(16, KSPLIT), 256>>>(Wm, Ws);
    reduce_kernel<<<(Bv*LOUT + 255)/256, 256>>>(bm, bs, out);
}